// round 7
// baseline (speedup 1.0000x reference)
#include <cuda_runtime.h>
#include <math.h>

// Problem constants
#define B_  64
#define T_  512
#define H_  1024
#define I_  1024
#define M_TOK (B_ * T_)

#define NBLK 128            // persistent blocks (1/SM, all co-resident)
#define NTHR 1024           // threads per persistent block
#define RS_STRIDE 33        // u64 stride for Rs rows (bank-conflict pad)
#define RS2_STRIDE 5        // u64 stride for Rs2 rows

typedef unsigned long long u64t;

// ---------------------------------------------------------------------------
// Packed fp32x2 helpers (FFMA2: 2 fp32 MACs per instruction)
// ---------------------------------------------------------------------------
__device__ __forceinline__ u64t ffma2(u64t a, u64t b, u64t c)
{
    u64t d;
    asm("fma.rn.f32x2 %0, %1, %2, %3;" : "=l"(d) : "l"(a), "l"(b), "l"(c));
    return d;
}
__device__ __forceinline__ u64t fadd2(u64t a, u64t b)
{
    u64t d;
    asm("add.rn.f32x2 %0, %1, %2;" : "=l"(d) : "l"(a), "l"(b));
    return d;
}
__device__ __forceinline__ u64t splat2(float x)
{
    u64t d;
    unsigned r = __float_as_uint(x);
    asm("mov.b64 %0, {%1, %2};" : "=l"(d) : "r"(r), "r"(r));
    return d;
}
__device__ __forceinline__ u64t pack2(float lo, float hi)
{
    u64t d;
    unsigned a = __float_as_uint(lo), b = __float_as_uint(hi);
    asm("mov.b64 %0, {%1, %2};" : "=l"(d) : "r"(a), "r"(b));
    return d;
}
__device__ __forceinline__ float2 unpack2(u64t p)
{
    unsigned lo, hi;
    asm("mov.b64 {%0, %1}, %2;" : "=r"(lo), "=r"(hi) : "l"(p));
    return make_float2(__uint_as_float(lo), __uint_as_float(hi));
}

// ---------------------------------------------------------------------------
// Scratch (__device__ globals; no allocation allowed)
// ---------------------------------------------------------------------------
__device__ float g_xw[M_TOK * H_];       // input-projection result
__device__ float g_y0[M_TOK * H_];       // layer-0 output sequence
__device__ float g_hT[2][H_ * B_];       // ping-pong hidden state, transposed h[k][b]
__device__ unsigned g_flags[NBLK * 32];  // per-block progress flags, 128B stride

// ---------------------------------------------------------------------------
// Input-projection GEMM: C[m][n] = sum_k A[m][k]*W[n][k] + b1[n] + b2[n]
// 128x128 tile, BK=16, 256 threads, 8x8/thread, FFMA2-packed over n.
// ---------------------------------------------------------------------------
__global__ __launch_bounds__(256) void gemm_bias_kernel(
    const float* __restrict__ A,
    const float* __restrict__ W,
    const float* __restrict__ b1,
    const float* __restrict__ b2,
    float* __restrict__ C,
    int M, int N, int K)
{
    __shared__ float As[16][128];
    __shared__ float Ws[16][128];

    const int m0 = blockIdx.y * 128;
    const int n0 = blockIdx.x * 128;
    const int tid = threadIdx.x;
    const int ty = tid >> 4;
    const int tx = tid & 15;

    const float* Ap = A + (size_t)m0 * K;
    const float* Wp = W + (size_t)n0 * K;

    const int f0  = tid;
    const int f1  = tid + 256;
    const int r0  = f0 >> 2, kq0 = (f0 & 3) * 4;
    const int r1  = f1 >> 2, kq1 = (f1 & 3) * 4;

    float4 pa0 = *(const float4*)(Ap + (size_t)r0 * K + kq0);
    float4 pa1 = *(const float4*)(Ap + (size_t)r1 * K + kq1);
    float4 pw0 = *(const float4*)(Wp + (size_t)r0 * K + kq0);
    float4 pw1 = *(const float4*)(Wp + (size_t)r1 * K + kq1);

    u64t acc2[8][4];
#pragma unroll
    for (int i = 0; i < 8; i++)
#pragma unroll
        for (int j = 0; j < 4; j++) acc2[i][j] = 0ull;

    for (int k0 = 0; k0 < K; k0 += 16) {
        As[kq0 + 0][r0] = pa0.x; As[kq0 + 1][r0] = pa0.y;
        As[kq0 + 2][r0] = pa0.z; As[kq0 + 3][r0] = pa0.w;
        As[kq1 + 0][r1] = pa1.x; As[kq1 + 1][r1] = pa1.y;
        As[kq1 + 2][r1] = pa1.z; As[kq1 + 3][r1] = pa1.w;
        Ws[kq0 + 0][r0] = pw0.x; Ws[kq0 + 1][r0] = pw0.y;
        Ws[kq0 + 2][r0] = pw0.z; Ws[kq0 + 3][r0] = pw0.w;
        Ws[kq1 + 0][r1] = pw1.x; Ws[kq1 + 1][r1] = pw1.y;
        Ws[kq1 + 2][r1] = pw1.z; Ws[kq1 + 3][r1] = pw1.w;
        __syncthreads();

        if (k0 + 16 < K) {
            int kn = k0 + 16;
            pa0 = *(const float4*)(Ap + (size_t)r0 * K + kn + kq0);
            pa1 = *(const float4*)(Ap + (size_t)r1 * K + kn + kq1);
            pw0 = *(const float4*)(Wp + (size_t)r0 * K + kn + kq0);
            pw1 = *(const float4*)(Wp + (size_t)r1 * K + kn + kq1);
        }

#pragma unroll
        for (int kk = 0; kk < 16; kk++) {
            float a[8];
            *(float4*)(a)     = *(const float4*)&As[kk][ty * 8];
            *(float4*)(a + 4) = *(const float4*)&As[kk][ty * 8 + 4];
            ulonglong2 wA = *(const ulonglong2*)&Ws[kk][tx * 8];
            ulonglong2 wB = *(const ulonglong2*)&Ws[kk][tx * 8 + 4];
            u64t w2[4] = { wA.x, wA.y, wB.x, wB.y };
#pragma unroll
            for (int i = 0; i < 8; i++) {
                u64t ap = splat2(a[i]);
#pragma unroll
                for (int j = 0; j < 4; j++)
                    acc2[i][j] = ffma2(ap, w2[j], acc2[i][j]);
            }
        }
        __syncthreads();
    }

    u64t bv2[4];
#pragma unroll
    for (int j = 0; j < 4; j++) {
        int n = n0 + tx * 8 + j * 2;
        bv2[j] = pack2(b1[n] + b2[n], b1[n + 1] + b2[n + 1]);
    }
#pragma unroll
    for (int i = 0; i < 8; i++) {
        int m = m0 + ty * 8 + i;
        float* cp = C + (size_t)m * N + n0 + tx * 8;
        ulonglong2 v0, v1;
        v0.x = fadd2(acc2[i][0], bv2[0]);
        v0.y = fadd2(acc2[i][1], bv2[1]);
        v1.x = fadd2(acc2[i][2], bv2[2]);
        v1.y = fadd2(acc2[i][3], bv2[3]);
        *(ulonglong2*)(cp)     = v0;
        *(ulonglong2*)(cp + 4) = v1;
    }
}

// ---------------------------------------------------------------------------
// Persistent recurrence kernel: one launch per layer, flag-dataflow sync.
// 128 blocks x 1024 threads. Block owns 8 output columns (c0..c0+7), full K.
//   warp w (0..31) = k-slice [32w, 32w+32); quarter q = w>>3 selects which
//   32 producer blocks this warp depends on. Per step each block posts ONE
//   monotonic flag after finalizing its columns; each warp polls only its
//   quarter's flags (1/lane) before computing -> no global barrier, skew <= 1
//   step, ping-pong h buffers make it safe.
// ---------------------------------------------------------------------------
__global__ __launch_bounds__(NTHR, 1) void rnn_layer_persistent(
    const float* __restrict__ Whh,    // [H, H]
    const float* __restrict__ xw,     // [B, T, H]
    float* __restrict__ y,            // [B, T, H]
    float* __restrict__ hlast)        // [B, H]
{
    extern __shared__ char smem[];
    u64t* Wsm = (u64t*)smem;                          // [H_*4]
    u64t* Rs  = (u64t*)(smem + H_ * 4 * 8);           // [256 * RS_STRIDE]
    u64t* Rs2 = Rs + 256 * RS_STRIDE;                 // [256 * RS2_STRIDE]

    const int tid = threadIdx.x;
    const int w   = tid >> 5;        // warp id = k-slice
    const int l   = tid & 31;        // lane = 2 batch rows
    const int c0  = blockIdx.x * 8;

    // ---- pack W columns into smem once per layer ----
    for (int idx = tid; idx < H_ * 4; idx += NTHR) {
        int k  = idx >> 2;
        int cp = idx & 3;
        float lo = Whh[(size_t)(c0 + 2 * cp)     * H_ + k];
        float hi = Whh[(size_t)(c0 + 2 * cp + 1) * H_ + k];
        Wsm[idx] = pack2(lo, hi);
    }

    // ---- zero initial hidden state (buffer 0) ----
    {
        int g = blockIdx.x * NTHR + tid;
        if (g < H_ * B_) g_hT[0][g] = 0.0f;
    }

    // ---- init full barrier (monotonic flags; seeds E0) ----
    const unsigned base = *(volatile unsigned*)&g_flags[blockIdx.x * 32];
    __syncthreads();
    if (tid == 0) {
        __threadfence();
        *(volatile unsigned*)&g_flags[blockIdx.x * 32] = base + 1;
    }
    if (tid < NBLK) {
        volatile unsigned* f = &g_flags[tid * 32];
        while ((int)(*f - (base + 1)) < 0) { }
    }
    __syncthreads();
    const unsigned E0 = base + 1;

    // per-warp dependency flag: quarter q covers producer blocks [32q, 32q+32)
    const int q = w >> 3;
    volatile unsigned* depf = &g_flags[(q * 32 + l) * 32];

    // finalize mapping (threads 0..255): o = tid = fcp*64 + fb
    const int fb  = tid & 63;
    const int fcp = tid >> 6;

    const int kbase = w * 32;

    for (int t = 0; t < T_; t++) {
        const float2* hin = (const float2*)g_hT[t & 1];
        float*        hout = g_hT[(t + 1) & 1];

        // ---- per-warp dataflow wait: my quarter's producers at step t ----
        {
            unsigned target = E0 + (unsigned)t;
            while (!__all_sync(0xFFFFFFFFu, (int)(*depf - target) >= 0)) { }
            __threadfence();   // acquire: order subsequent h reads
        }

        // prefetch xw for finalize
        u64t xv = 0ull;
        if (tid < 256)
            xv = *(const u64t*)&xw[((size_t)fb * T_ + t) * H_ + c0 + fcp * 2];

        // ---- main loop: this warp's k-slice, 2b x 8c per lane ----
        u64t acc00 = 0, acc01 = 0, acc02 = 0, acc03 = 0;   // b = 2l
        u64t acc10 = 0, acc11 = 0, acc12 = 0, acc13 = 0;   // b = 2l+1
#pragma unroll 8
        for (int i = 0; i < 32; i++) {
            int k = kbase + i;
            float2 h2 = __ldcg(&hin[k * 32 + l]);
            ulonglong2 wv0 = *(const ulonglong2*)&Wsm[k * 4];
            ulonglong2 wv1 = *(const ulonglong2*)&Wsm[k * 4 + 2];
            u64t a0 = splat2(h2.x);
            u64t a1 = splat2(h2.y);
            acc00 = ffma2(a0, wv0.x, acc00);
            acc01 = ffma2(a0, wv0.y, acc01);
            acc02 = ffma2(a0, wv1.x, acc02);
            acc03 = ffma2(a0, wv1.y, acc03);
            acc10 = ffma2(a1, wv0.x, acc10);
            acc11 = ffma2(a1, wv0.y, acc11);
            acc12 = ffma2(a1, wv1.x, acc12);
            acc13 = ffma2(a1, wv1.y, acc13);
        }

        // ---- dump per-warp partials to smem ----
        {
            int b0 = 2 * l, b1 = 2 * l + 1;
            Rs[(0 * 64 + b0) * RS_STRIDE + w] = acc00;
            Rs[(1 * 64 + b0) * RS_STRIDE + w] = acc01;
            Rs[(2 * 64 + b0) * RS_STRIDE + w] = acc02;
            Rs[(3 * 64 + b0) * RS_STRIDE + w] = acc03;
            Rs[(0 * 64 + b1) * RS_STRIDE + w] = acc10;
            Rs[(1 * 64 + b1) * RS_STRIDE + w] = acc11;
            Rs[(2 * 64 + b1) * RS_STRIDE + w] = acc12;
            Rs[(3 * 64 + b1) * RS_STRIDE + w] = acc13;
        }
        __syncthreads();

        // ---- stage 1: all 1024 threads each sum 8 of 32 k-slices ----
        {
            int o  = tid & 255;
            int qq = tid >> 8;          // 0..3
            const u64t* row = &Rs[o * RS_STRIDE + qq * 8];
            u64t s01 = fadd2(row[0], row[1]);
            u64t s23 = fadd2(row[2], row[3]);
            u64t s45 = fadd2(row[4], row[5]);
            u64t s67 = fadd2(row[6], row[7]);
            Rs2[o * RS2_STRIDE + qq] = fadd2(fadd2(s01, s23), fadd2(s45, s67));
        }
        __syncthreads();

        // ---- stage 2: threads 0..255 finish, tanh, store ----
        if (tid < 256) {
            const u64t* r2 = &Rs2[tid * RS2_STRIDE];
            u64t s = fadd2(fadd2(r2[0], r2[1]), fadd2(r2[2], r2[3]));
            s = fadd2(s, xv);
            float2 sv = unpack2(s);
            float v0 = tanhf(sv.x);
            float v1 = tanhf(sv.y);
            int cA = c0 + fcp * 2;
            hout[(cA)     * 64 + fb] = v0;      // transposed, coalesced over fb
            hout[(cA + 1) * 64 + fb] = v1;
            *(u64t*)&y[((size_t)fb * T_ + t) * H_ + cA] = pack2(v0, v1);
            if (t == T_ - 1)
                *(u64t*)&hlast[(size_t)fb * H_ + cA] = pack2(v0, v1);
        }
        __syncthreads();

        // ---- post this block's progress flag ----
        if (tid == 0) {
            __threadfence();
            *(volatile unsigned*)&g_flags[blockIdx.x * 32] = E0 + (unsigned)t + 1;
        }
    }
}

// ---------------------------------------------------------------------------
// Launcher: 4 graph nodes.
// ---------------------------------------------------------------------------
extern "C" void kernel_launch(void* const* d_in, const int* in_sizes, int n_in,
                              void* d_out, int out_size)
{
    const float* X     = (const float*)d_in[0];
    const float* W_ih0 = (const float*)d_in[1];
    const float* b_ih0 = (const float*)d_in[2];
    const float* W_hh0 = (const float*)d_in[3];
    const float* b_hh0 = (const float*)d_in[4];
    const float* W_ih1 = (const float*)d_in[5];
    const float* b_ih1 = (const float*)d_in[6];
    const float* W_hh1 = (const float*)d_in[7];
    const float* b_hh1 = (const float*)d_in[8];

    float* out    = (float*)d_out;
    float* y_out  = out;                       // [B, T, H]
    float* h_last = out + (size_t)M_TOK * H_;  // [2, B, H]

    float* xw = nullptr;
    float* y0 = nullptr;
    cudaGetSymbolAddress((void**)&xw, g_xw);
    cudaGetSymbolAddress((void**)&y0, g_y0);

    const int rnn_smem = H_ * 4 * 8                 // Wsm 32 KB
                       + 256 * RS_STRIDE * 8        // Rs  67.6 KB
                       + 256 * RS2_STRIDE * 8;      // Rs2 10 KB
    static int attr_set = 0;
    if (!attr_set) {
        cudaFuncSetAttribute(rnn_layer_persistent,
                             cudaFuncAttributeMaxDynamicSharedMemorySize, rnn_smem);
        attr_set = 1;
    }

    dim3 ggrid(H_ / 128, M_TOK / 128);   // (8, 256)

    // ---------------- layer 0 ----------------
    gemm_bias_kernel<<<ggrid, 256>>>(X, W_ih0, b_ih0, b_hh0, xw, M_TOK, H_, I_);
    rnn_layer_persistent<<<NBLK, NTHR, rnn_smem>>>(W_hh0, xw, y0, h_last);

    // ---------------- layer 1 ----------------
    gemm_bias_kernel<<<ggrid, 256>>>(y0, W_ih1, b_ih1, b_hh1, xw, M_TOK, H_, H_);
    rnn_layer_persistent<<<NBLK, NTHR, rnn_smem>>>(W_hh1, xw, y_out, h_last + B_ * H_);
}

// round 8
// speedup vs baseline: 1.6133x; 1.6133x over previous
#include <cuda_runtime.h>
#include <math.h>

// Problem constants
#define B_  64
#define T_  512
#define H_  1024
#define I_  1024
#define M_TOK (B_ * T_)

#define NBLK 128            // persistent blocks (1/SM, all co-resident)
#define NTHR 1024           // threads per persistent block
#define RS_STRIDE 33        // u64 stride for Rs rows (bank-conflict pad)
#define RS2_STRIDE 5        // u64 stride for Rs2 rows

typedef unsigned long long u64t;

// ---------------------------------------------------------------------------
// Packed fp32x2 helpers (FFMA2: 2 fp32 MACs per instruction)
// ---------------------------------------------------------------------------
__device__ __forceinline__ u64t ffma2(u64t a, u64t b, u64t c)
{
    u64t d;
    asm("fma.rn.f32x2 %0, %1, %2, %3;" : "=l"(d) : "l"(a), "l"(b), "l"(c));
    return d;
}
__device__ __forceinline__ u64t fadd2(u64t a, u64t b)
{
    u64t d;
    asm("add.rn.f32x2 %0, %1, %2;" : "=l"(d) : "l"(a), "l"(b));
    return d;
}
__device__ __forceinline__ u64t splat2(float x)
{
    u64t d;
    unsigned r = __float_as_uint(x);
    asm("mov.b64 %0, {%1, %2};" : "=l"(d) : "r"(r), "r"(r));
    return d;
}
__device__ __forceinline__ u64t pack2(float lo, float hi)
{
    u64t d;
    unsigned a = __float_as_uint(lo), b = __float_as_uint(hi);
    asm("mov.b64 %0, {%1, %2};" : "=l"(d) : "r"(a), "r"(b));
    return d;
}
__device__ __forceinline__ float2 unpack2(u64t p)
{
    unsigned lo, hi;
    asm("mov.b64 {%0, %1}, %2;" : "=r"(lo), "=r"(hi) : "l"(p));
    return make_float2(__uint_as_float(lo), __uint_as_float(hi));
}

// ---------------------------------------------------------------------------
// Scratch (__device__ globals; no allocation allowed)
// ---------------------------------------------------------------------------
__device__ float g_xw[M_TOK * H_];        // layer-0 input projection
__device__ float g_h0T[2][H_ * B_];       // layer-0 hidden, transposed h[k][b], ping-pong
__device__ float g_h1T[2][H_ * B_];       // layer-1 hidden, transposed
__device__ unsigned g_flags[NBLK * 32];   // barrier flags, 128B stride (zero-init)

// Distributed grid barrier (proven in round 5): every block posts its flag,
// 128 threads/block poll all flags. Monotonic generations -> replay-safe.
__device__ __forceinline__ void grid_barrier(unsigned gen)
{
    __syncthreads();
    if (threadIdx.x == 0) {
        __threadfence();                                  // release prior stores
        *(volatile unsigned*)&g_flags[blockIdx.x * 32] = gen;
    }
    if (threadIdx.x < NBLK) {
        volatile unsigned* f = &g_flags[threadIdx.x * 32];
        while ((int)(*f - gen) < 0) { }
        __threadfence();                                  // acquire
    }
    __syncthreads();
}

// ---------------------------------------------------------------------------
// Input-projection GEMM (layer 0 only): C = X @ W_ih0^T + b_ih0 + b_hh0
// 128x128 tile, BK=16, 256 threads, 8x8/thread, FFMA2-packed over n.
// ---------------------------------------------------------------------------
__global__ __launch_bounds__(256) void gemm_bias_kernel(
    const float* __restrict__ A,
    const float* __restrict__ W,
    const float* __restrict__ b1,
    const float* __restrict__ b2,
    float* __restrict__ C,
    int M, int N, int K)
{
    __shared__ float As[16][128];
    __shared__ float Ws[16][128];

    const int m0 = blockIdx.y * 128;
    const int n0 = blockIdx.x * 128;
    const int tid = threadIdx.x;
    const int ty = tid >> 4;
    const int tx = tid & 15;

    const float* Ap = A + (size_t)m0 * K;
    const float* Wp = W + (size_t)n0 * K;

    const int f0  = tid;
    const int f1  = tid + 256;
    const int r0  = f0 >> 2, kq0 = (f0 & 3) * 4;
    const int r1  = f1 >> 2, kq1 = (f1 & 3) * 4;

    float4 pa0 = *(const float4*)(Ap + (size_t)r0 * K + kq0);
    float4 pa1 = *(const float4*)(Ap + (size_t)r1 * K + kq1);
    float4 pw0 = *(const float4*)(Wp + (size_t)r0 * K + kq0);
    float4 pw1 = *(const float4*)(Wp + (size_t)r1 * K + kq1);

    u64t acc2[8][4];
#pragma unroll
    for (int i = 0; i < 8; i++)
#pragma unroll
        for (int j = 0; j < 4; j++) acc2[i][j] = 0ull;

    for (int k0 = 0; k0 < K; k0 += 16) {
        As[kq0 + 0][r0] = pa0.x; As[kq0 + 1][r0] = pa0.y;
        As[kq0 + 2][r0] = pa0.z; As[kq0 + 3][r0] = pa0.w;
        As[kq1 + 0][r1] = pa1.x; As[kq1 + 1][r1] = pa1.y;
        As[kq1 + 2][r1] = pa1.z; As[kq1 + 3][r1] = pa1.w;
        Ws[kq0 + 0][r0] = pw0.x; Ws[kq0 + 1][r0] = pw0.y;
        Ws[kq0 + 2][r0] = pw0.z; Ws[kq0 + 3][r0] = pw0.w;
        Ws[kq1 + 0][r1] = pw1.x; Ws[kq1 + 1][r1] = pw1.y;
        Ws[kq1 + 2][r1] = pw1.z; Ws[kq1 + 3][r1] = pw1.w;
        __syncthreads();

        if (k0 + 16 < K) {
            int kn = k0 + 16;
            pa0 = *(const float4*)(Ap + (size_t)r0 * K + kn + kq0);
            pa1 = *(const float4*)(Ap + (size_t)r1 * K + kn + kq1);
            pw0 = *(const float4*)(Wp + (size_t)r0 * K + kn + kq0);
            pw1 = *(const float4*)(Wp + (size_t)r1 * K + kn + kq1);
        }

#pragma unroll
        for (int kk = 0; kk < 16; kk++) {
            float a[8];
            *(float4*)(a)     = *(const float4*)&As[kk][ty * 8];
            *(float4*)(a + 4) = *(const float4*)&As[kk][ty * 8 + 4];
            ulonglong2 wA = *(const ulonglong2*)&Ws[kk][tx * 8];
            ulonglong2 wB = *(const ulonglong2*)&Ws[kk][tx * 8 + 4];
            u64t w2[4] = { wA.x, wA.y, wB.x, wB.y };
#pragma unroll
            for (int i = 0; i < 8; i++) {
                u64t ap = splat2(a[i]);
#pragma unroll
                for (int j = 0; j < 4; j++)
                    acc2[i][j] = ffma2(ap, w2[j], acc2[i][j]);
            }
        }
        __syncthreads();
    }

    u64t bv2[4];
#pragma unroll
    for (int j = 0; j < 4; j++) {
        int n = n0 + tx * 8 + j * 2;
        bv2[j] = pack2(b1[n] + b2[n], b1[n + 1] + b2[n + 1]);
    }
#pragma unroll
    for (int i = 0; i < 8; i++) {
        int m = m0 + ty * 8 + i;
        float* cp = C + (size_t)m * N + n0 + tx * 8;
        ulonglong2 v0, v1;
        v0.x = fadd2(acc2[i][0], bv2[0]);
        v0.y = fadd2(acc2[i][1], bv2[1]);
        v1.x = fadd2(acc2[i][2], bv2[2]);
        v1.y = fadd2(acc2[i][3], bv2[3]);
        *(ulonglong2*)(cp)     = v0;
        *(ulonglong2*)(cp + 4) = v1;
    }
}

// ---------------------------------------------------------------------------
// Fused two-layer pipelined recurrence. One launch for BOTH layers.
// Tick u (0..T): layer-0 step u (u<T) and layer-1 step u-1 (u>0), then ONE
// grid barrier. Layer-1 consumes y0[t] directly from the transposed h0
// ping-pong buffer (no y0 materialization, no second projection GEMM); its
// input projection is fused as K=2048: [W_ih1 | W_hh1] . [y0_t ; h1].
// Block owns 8 output columns for BOTH layers. Warp w = k-slice [32w,32w+32).
// ---------------------------------------------------------------------------
__global__ __launch_bounds__(NTHR, 1) void rnn_fused_pipelined(
    const float* __restrict__ Whh0,   // [H, H]
    const float* __restrict__ xw0,    // [B, T, H]  (layer-0 xw incl. biases)
    const float* __restrict__ Wih1,   // [H, H]
    const float* __restrict__ Whh1,   // [H, H]
    const float* __restrict__ bih1,   // [H]
    const float* __restrict__ bhh1,   // [H]
    float* __restrict__ y,            // [B, T, H]  final output (layer-1 seq)
    float* __restrict__ hlast0,       // [B, H]
    float* __restrict__ hlast1)       // [B, H]
{
    extern __shared__ char smem[];
    u64t* W0  = (u64t*)smem;                          // [H_*4] l0 W_hh col-pairs
    u64t* Wi1 = W0  + H_ * 4;                         // [H_*4] l1 W_ih col-pairs
    u64t* Wh1 = Wi1 + H_ * 4;                         // [H_*4] l1 W_hh col-pairs
    u64t* Rs  = Wh1 + H_ * 4;                         // [256 * RS_STRIDE]
    u64t* Rs2 = Rs  + 256 * RS_STRIDE;                // [256 * RS2_STRIDE]

    const int tid = threadIdx.x;
    const int w   = tid >> 5;        // warp id = k-slice
    const int l   = tid & 31;        // lane = 2 batch rows
    const int c0  = blockIdx.x * 8;

    // ---- pack weight columns into smem once ----
    for (int idx = tid; idx < H_ * 4; idx += NTHR) {
        int k  = idx >> 2;
        int cp = idx & 3;
        int cA = c0 + 2 * cp, cB = cA + 1;
        W0 [idx] = pack2(Whh0[(size_t)cA * H_ + k], Whh0[(size_t)cB * H_ + k]);
        Wi1[idx] = pack2(Wih1[(size_t)cA * H_ + k], Wih1[(size_t)cB * H_ + k]);
        Wh1[idx] = pack2(Whh1[(size_t)cA * H_ + k], Whh1[(size_t)cB * H_ + k]);
    }

    // ---- zero initial hidden states (buffer 0) ----
    {
        int g = blockIdx.x * NTHR + tid;
        if (g < H_ * B_) { g_h0T[0][g] = 0.0f; g_h1T[0][g] = 0.0f; }
    }

    // finalize mapping (threads 0..255): o = tid = fcp*64 + fb
    const int fb  = tid & 63;
    const int fcp = tid >> 6;
    const int cA  = c0 + fcp * 2;

    // layer-1 bias pair (resident in register)
    u64t b1p = 0ull;
    if (tid < 256)
        b1p = pack2(bih1[cA] + bhh1[cA], bih1[cA + 1] + bhh1[cA + 1]);

    // ---- barrier generation seed (monotonic across replays) ----
    unsigned gen = *(volatile unsigned*)&g_flags[blockIdx.x * 32] + 1;
    grid_barrier(gen++);

    const int kbase = w * 32;

    for (int u = 0; u <= T_; u++) {
        // ================= layer 0, step u =================
        if (u < T_) {
            const float2* hin  = (const float2*)g_h0T[u & 1];
            float*        hout = g_h0T[(u + 1) & 1];

            u64t xv = 0ull;
            if (tid < 256)
                xv = __ldcg((const u64t*)&xw0[((size_t)fb * T_ + u) * H_ + cA]);

            u64t a00 = 0, a01 = 0, a02 = 0, a03 = 0;
            u64t a10 = 0, a11 = 0, a12 = 0, a13 = 0;
#pragma unroll 8
            for (int i = 0; i < 32; i++) {
                int k = kbase + i;
                float2 h2 = __ldcg(&hin[k * 32 + l]);
                ulonglong2 wv0 = *(const ulonglong2*)&W0[k * 4];
                ulonglong2 wv1 = *(const ulonglong2*)&W0[k * 4 + 2];
                u64t p0 = splat2(h2.x);
                u64t p1 = splat2(h2.y);
                a00 = ffma2(p0, wv0.x, a00); a01 = ffma2(p0, wv0.y, a01);
                a02 = ffma2(p0, wv1.x, a02); a03 = ffma2(p0, wv1.y, a03);
                a10 = ffma2(p1, wv0.x, a10); a11 = ffma2(p1, wv0.y, a11);
                a12 = ffma2(p1, wv1.x, a12); a13 = ffma2(p1, wv1.y, a13);
            }
            {
                int b0 = 2 * l, b1i = 2 * l + 1;
                Rs[(0 * 64 + b0) * RS_STRIDE + w] = a00;
                Rs[(1 * 64 + b0) * RS_STRIDE + w] = a01;
                Rs[(2 * 64 + b0) * RS_STRIDE + w] = a02;
                Rs[(3 * 64 + b0) * RS_STRIDE + w] = a03;
                Rs[(0 * 64 + b1i) * RS_STRIDE + w] = a10;
                Rs[(1 * 64 + b1i) * RS_STRIDE + w] = a11;
                Rs[(2 * 64 + b1i) * RS_STRIDE + w] = a12;
                Rs[(3 * 64 + b1i) * RS_STRIDE + w] = a13;
            }
            __syncthreads();
            {   // stage 1: 1024 threads, each sums 8 of 32 k-slices
                int o  = tid & 255;
                int qq = tid >> 8;
                const u64t* row = &Rs[o * RS_STRIDE + qq * 8];
                u64t s01 = fadd2(row[0], row[1]);
                u64t s23 = fadd2(row[2], row[3]);
                u64t s45 = fadd2(row[4], row[5]);
                u64t s67 = fadd2(row[6], row[7]);
                Rs2[o * RS2_STRIDE + qq] = fadd2(fadd2(s01, s23), fadd2(s45, s67));
            }
            __syncthreads();
            if (tid < 256) {
                const u64t* r2 = &Rs2[tid * RS2_STRIDE];
                u64t s = fadd2(fadd2(r2[0], r2[1]), fadd2(r2[2], r2[3]));
                s = fadd2(s, xv);
                float2 sv = unpack2(s);
                float v0 = tanhf(sv.x);
                float v1 = tanhf(sv.y);
                hout[(cA)     * 64 + fb] = v0;
                hout[(cA + 1) * 64 + fb] = v1;
                if (u == T_ - 1)
                    *(u64t*)&hlast0[(size_t)fb * H_ + cA] = pack2(v0, v1);
            }
        }

        // ================= layer 1, step u-1 =================
        if (u > 0) {
            int t = u - 1;
            const float2* xin  = (const float2*)g_h0T[u & 1];       // y0[t]^T
            const float2* hin  = (const float2*)g_h1T[t & 1];
            float*        hout = g_h1T[(t + 1) & 1];

            __syncthreads();     // Rs/Rs2 free (l0 stage2 done)

            u64t a00 = 0, a01 = 0, a02 = 0, a03 = 0;
            u64t a10 = 0, a11 = 0, a12 = 0, a13 = 0;
#pragma unroll 4
            for (int i = 0; i < 32; i++) {
                int k = kbase + i;
                // interleaved: input-projection slice + recurrent slice
                float2 x2 = __ldcg(&xin[k * 32 + l]);
                float2 h2 = __ldcg(&hin[k * 32 + l]);
                ulonglong2 iv0 = *(const ulonglong2*)&Wi1[k * 4];
                ulonglong2 iv1 = *(const ulonglong2*)&Wi1[k * 4 + 2];
                ulonglong2 hv0 = *(const ulonglong2*)&Wh1[k * 4];
                ulonglong2 hv1 = *(const ulonglong2*)&Wh1[k * 4 + 2];
                u64t px0 = splat2(x2.x), px1 = splat2(x2.y);
                u64t ph0 = splat2(h2.x), ph1 = splat2(h2.y);
                a00 = ffma2(px0, iv0.x, a00); a01 = ffma2(px0, iv0.y, a01);
                a02 = ffma2(px0, iv1.x, a02); a03 = ffma2(px0, iv1.y, a03);
                a10 = ffma2(px1, iv0.x, a10); a11 = ffma2(px1, iv0.y, a11);
                a12 = ffma2(px1, iv1.x, a12); a13 = ffma2(px1, iv1.y, a13);
                a00 = ffma2(ph0, hv0.x, a00); a01 = ffma2(ph0, hv0.y, a01);
                a02 = ffma2(ph0, hv1.x, a02); a03 = ffma2(ph0, hv1.y, a03);
                a10 = ffma2(ph1, hv0.x, a10); a11 = ffma2(ph1, hv0.y, a11);
                a12 = ffma2(ph1, hv1.x, a12); a13 = ffma2(ph1, hv1.y, a13);
            }
            {
                int b0 = 2 * l, b1i = 2 * l + 1;
                Rs[(0 * 64 + b0) * RS_STRIDE + w] = a00;
                Rs[(1 * 64 + b0) * RS_STRIDE + w] = a01;
                Rs[(2 * 64 + b0) * RS_STRIDE + w] = a02;
                Rs[(3 * 64 + b0) * RS_STRIDE + w] = a03;
                Rs[(0 * 64 + b1i) * RS_STRIDE + w] = a10;
                Rs[(1 * 64 + b1i) * RS_STRIDE + w] = a11;
                Rs[(2 * 64 + b1i) * RS_STRIDE + w] = a12;
                Rs[(3 * 64 + b1i) * RS_STRIDE + w] = a13;
            }
            __syncthreads();
            {
                int o  = tid & 255;
                int qq = tid >> 8;
                const u64t* row = &Rs[o * RS_STRIDE + qq * 8];
                u64t s01 = fadd2(row[0], row[1]);
                u64t s23 = fadd2(row[2], row[3]);
                u64t s45 = fadd2(row[4], row[5]);
                u64t s67 = fadd2(row[6], row[7]);
                Rs2[o * RS2_STRIDE + qq] = fadd2(fadd2(s01, s23), fadd2(s45, s67));
            }
            __syncthreads();
            if (tid < 256) {
                const u64t* r2 = &Rs2[tid * RS2_STRIDE];
                u64t s = fadd2(fadd2(r2[0], r2[1]), fadd2(r2[2], r2[3]));
                s = fadd2(s, b1p);
                float2 sv = unpack2(s);
                float v0 = tanhf(sv.x);
                float v1 = tanhf(sv.y);
                hout[(cA)     * 64 + fb] = v0;
                hout[(cA + 1) * 64 + fb] = v1;
                *(u64t*)&y[((size_t)fb * T_ + t) * H_ + cA] = pack2(v0, v1);
                if (t == T_ - 1)
                    *(u64t*)&hlast1[(size_t)fb * H_ + cA] = pack2(v0, v1);
            }
        }

        grid_barrier(gen++);
    }
}

// ---------------------------------------------------------------------------
// Launcher: 2 graph nodes.
// ---------------------------------------------------------------------------
extern "C" void kernel_launch(void* const* d_in, const int* in_sizes, int n_in,
                              void* d_out, int out_size)
{
    const float* X     = (const float*)d_in[0];
    const float* W_ih0 = (const float*)d_in[1];
    const float* b_ih0 = (const float*)d_in[2];
    const float* W_hh0 = (const float*)d_in[3];
    const float* b_hh0 = (const float*)d_in[4];
    const float* W_ih1 = (const float*)d_in[5];
    const float* b_ih1 = (const float*)d_in[6];
    const float* W_hh1 = (const float*)d_in[7];
    const float* b_hh1 = (const float*)d_in[8];

    float* out    = (float*)d_out;
    float* y_out  = out;                       // [B, T, H]
    float* h_last = out + (size_t)M_TOK * H_;  // [2, B, H]

    float* xw = nullptr;
    cudaGetSymbolAddress((void**)&xw, g_xw);

    const int rnn_smem = 3 * H_ * 4 * 8            // W0/Wi1/Wh1 96 KB
                       + 256 * RS_STRIDE * 8       // Rs  67.6 KB
                       + 256 * RS2_STRIDE * 8;     // Rs2 10 KB
    static int attr_set = 0;
    if (!attr_set) {
        cudaFuncSetAttribute(rnn_fused_pipelined,
                             cudaFuncAttributeMaxDynamicSharedMemorySize, rnn_smem);
        attr_set = 1;
    }

    dim3 ggrid(H_ / 128, M_TOK / 128);   // (8, 256)

    gemm_bias_kernel<<<ggrid, 256>>>(X, W_ih0, b_ih0, b_hh0, xw, M_TOK, H_, I_);
    rnn_fused_pipelined<<<NBLK, NTHR, rnn_smem>>>(
        W_hh0, xw, W_ih1, W_hh1, b_ih1, b_hh1,
        y_out, h_last, h_last + B_ * H_);
}